// round 2
// baseline (speedup 1.0000x reference)
#include <cuda_runtime.h>

#define NMAX 50000
#define EMAX 800000

// ---- scratch (static __device__ per allocation rules) ----
__device__ float4 g_src_a[NMAX];        // a_src per head (4)
__device__ float4 g_src_x[NMAX];        // x0, x1, -, -
__device__ float4 g_adst[NMAX];         // a_dst per head (4)
__device__ float4 g_accum[NMAX * 3];    // [denom(4)][T0(4)][T1(4)] per node
__device__ float  g_consts[20];         // s0[4] s1[4] d0[4] d1[4] g[4]
__device__ float  g_easum;

// K0: per-head attention constants (256 threads = H*C)
__global__ void k_head(const float* __restrict__ W, const float* __restrict__ att_src,
                       const float* __restrict__ att_dst, const float* __restrict__ W_edge,
                       const float* __restrict__ att_edge) {
    int t = threadIdx.x;        // t = h*64 + c
    int h = t >> 6;
    __shared__ float sh[5][256];
    float w0 = W[2 * t], w1 = W[2 * t + 1];
    float as = att_src[t], ad = att_dst[t];
    sh[0][t] = w0 * as;
    sh[1][t] = w1 * as;
    sh[2][t] = w0 * ad;
    sh[3][t] = w1 * ad;
    sh[4][t] = W_edge[t] * att_edge[t];
    __syncthreads();
    for (int off = 32; off >= 1; off >>= 1) {
        if ((t & 63) < off) {
            #pragma unroll
            for (int k = 0; k < 5; k++) sh[k][t] += sh[k][t + off];
        }
        __syncthreads();
    }
    if ((t & 63) == 0) {
        #pragma unroll
        for (int k = 0; k < 5; k++) g_consts[k * 4 + h] = sh[k][t];
    }
    if (t == 0) g_easum = 0.f;
}

// K1: sum of edge_attr (for self-loop mean)
__global__ void k_easum(const float* __restrict__ ea, int E) {
    float v = 0.f;
    for (int i = blockIdx.x * blockDim.x + threadIdx.x; i < E; i += gridDim.x * blockDim.x)
        v += ea[i];
    #pragma unroll
    for (int o = 16; o; o >>= 1) v += __shfl_down_sync(0xffffffffu, v, o);
    __shared__ float sh[8];
    if ((threadIdx.x & 31) == 0) sh[threadIdx.x >> 5] = v;
    __syncthreads();
    if (threadIdx.x == 0) {
        float s = 0.f;
        #pragma unroll
        for (int i = 0; i < 8; i++) s += sh[i];
        atomicAdd(&g_easum, s);
    }
}

// K2: per-node packed attention scalars + zero accumulators
__global__ void k_node(const float* __restrict__ x, int N) {
    int n = blockIdx.x * blockDim.x + threadIdx.x;
    if (n >= N) return;
    float x0 = x[2 * n], x1 = x[2 * n + 1];
    float4 as, ad;
    as.x = x0 * g_consts[0] + x1 * g_consts[4];
    as.y = x0 * g_consts[1] + x1 * g_consts[5];
    as.z = x0 * g_consts[2] + x1 * g_consts[6];
    as.w = x0 * g_consts[3] + x1 * g_consts[7];
    ad.x = x0 * g_consts[8]  + x1 * g_consts[12];
    ad.y = x0 * g_consts[9]  + x1 * g_consts[13];
    ad.z = x0 * g_consts[10] + x1 * g_consts[14];
    ad.w = x0 * g_consts[11] + x1 * g_consts[15];
    g_src_a[n] = as;
    g_adst[n] = ad;
    g_src_x[n] = make_float4(x0, x1, 0.f, 0.f);
    float4 z = make_float4(0.f, 0.f, 0.f, 0.f);
    g_accum[n * 3 + 0] = z;
    g_accum[n * 3 + 1] = z;
    g_accum[n * 3 + 2] = z;
}

__device__ __forceinline__ void red_v4(float4* p, float a, float b, float c, float d) {
    asm volatile("red.global.add.v4.f32 [%0], {%1,%2,%3,%4};"
                 :: "l"(p), "f"(a), "f"(b), "f"(c), "f"(d) : "memory");
}

// K3: edge pass — softmax weights + factored message accumulation
// edge_index arrives as int32 (JAX x64-disabled downcasts the int64 request).
__global__ void k_edge(const int* __restrict__ ei, const float* __restrict__ ea,
                       int E, int N) {
    int e = blockIdx.x * blockDim.x + threadIdx.x;
    if (e >= E) return;
    int src = ei[e];
    int dst = ei[E + e];
    if ((unsigned)src >= (unsigned)N || (unsigned)dst >= (unsigned)N) return;  // safety
    float w = ea[e];
    float4 as = g_src_a[src];
    float4 ad = g_adst[dst];
    float4 xs = g_src_x[src];
    float g0 = g_consts[16], g1 = g_consts[17], g2 = g_consts[18], g3 = g_consts[19];

    float a0 = as.x + ad.x + w * g0; a0 = fmaxf(a0, 0.2f * a0);
    float a1 = as.y + ad.y + w * g1; a1 = fmaxf(a1, 0.2f * a1);
    float a2 = as.z + ad.z + w * g2; a2 = fmaxf(a2, 0.2f * a2);
    float a3 = as.w + ad.w + w * g3; a3 = fmaxf(a3, 0.2f * a3);
    float e0 = __expf(a0), e1 = __expf(a1), e2 = __expf(a2), e3 = __expf(a3);

    float4* base = &g_accum[dst * 3];
    red_v4(base,     e0,        e1,        e2,        e3);
    red_v4(base + 1, e0 * xs.x, e1 * xs.x, e2 * xs.x, e3 * xs.x);
    red_v4(base + 2, e0 * xs.y, e1 * xs.y, e2 * xs.y, e3 * xs.y);
}

// K4: per-node expansion to [N, 256], self-loop folded in analytically
__global__ void k_out(const float* __restrict__ W, const float* __restrict__ bias,
                      float* __restrict__ out, int N, float invE) {
    int hc = threadIdx.x;       // 0..255
    int h = hc >> 6;
    float w0 = W[2 * hc], w1 = W[2 * hc + 1], b = bias[hc];
    float mean = g_easum * invE;
    float gh = g_consts[16 + h];
    for (int n = blockIdx.x; n < N; n += gridDim.x) {
        float4 as4 = g_src_a[n];
        float4 ad4 = g_adst[n];
        float4 xs  = g_src_x[n];
        float4 d4  = g_accum[n * 3 + 0];
        float4 t04 = g_accum[n * 3 + 1];
        float4 t14 = g_accum[n * 3 + 2];
        float ash = (h == 0) ? as4.x : (h == 1) ? as4.y : (h == 2) ? as4.z : as4.w;
        float adh = (h == 0) ? ad4.x : (h == 1) ? ad4.y : (h == 2) ? ad4.z : ad4.w;
        float dh  = (h == 0) ? d4.x  : (h == 1) ? d4.y  : (h == 2) ? d4.z  : d4.w;
        float t0h = (h == 0) ? t04.x : (h == 1) ? t04.y : (h == 2) ? t04.z : t04.w;
        float t1h = (h == 0) ? t14.x : (h == 1) ? t14.y : (h == 2) ? t14.z : t14.w;

        float a = ash + adh + mean * gh;        // self-loop logit
        a = fmaxf(a, 0.2f * a);
        float ws = __expf(a);
        float denom = dh + ws;
        float T0 = t0h + ws * xs.x;
        float T1 = t1h + ws * xs.y;
        out[(size_t)n * 256 + hc] = (T0 * w0 + T1 * w1) / denom + b;
    }
}

extern "C" void kernel_launch(void* const* d_in, const int* in_sizes, int n_in,
                              void* d_out, int out_size) {
    const float* x        = (const float*)d_in[0];
    const int*   ei       = (const int*)d_in[1];     // int32 (JAX x64 off)
    const float* ea       = (const float*)d_in[2];
    const float* W        = (const float*)d_in[3];
    const float* att_src  = (const float*)d_in[4];
    const float* att_dst  = (const float*)d_in[5];
    const float* W_edge   = (const float*)d_in[6];
    const float* att_edge = (const float*)d_in[7];
    const float* bias     = (const float*)d_in[8];
    int N = in_sizes[0] / 2;
    int E = in_sizes[2];
    float* out = (float*)d_out;

    k_head<<<1, 256>>>(W, att_src, att_dst, W_edge, att_edge);
    k_easum<<<256, 256>>>(ea, E);
    k_node<<<(N + 255) / 256, 256>>>(x, N);
    k_edge<<<(E + 255) / 256, 256>>>(ei, ea, E, N);
    k_out<<<2048, 256>>>(W, bias, out, N, 1.0f / (float)E);
}

// round 3
// speedup vs baseline: 1.5000x; 1.5000x over previous
#include <cuda_runtime.h>

#define NMAX 50000

// ---- scratch (static __device__ per allocation rules) ----
// per-node src-side pack: [2n] = a_src(4 heads), [2n+1] = {x0, x1, 0, 0} (32B together)
__device__ __align__(32) float4 g_srcpack[NMAX * 2];
__device__ float4 g_adst[NMAX];         // a_dst per head (4)
__device__ float4 g_accum[NMAX * 3];    // [denom(4)][T0(4)][T1(4)] per node
__device__ float  g_consts[20];         // s0[4] s1[4] d0[4] d1[4] g[4]
__device__ float  g_easum;

// K0: fused constants + per-node pack + accumulator zero + g_easum zero.
// Every block recomputes the 20 head constants (cheap, L2-cached reads).
__global__ void k_prep(const float* __restrict__ x, const float* __restrict__ W,
                       const float* __restrict__ att_src, const float* __restrict__ att_dst,
                       const float* __restrict__ W_edge, const float* __restrict__ att_edge,
                       int N) {
    __shared__ float sh[5][256];
    __shared__ float cs[20];
    int t = threadIdx.x;        // t = h*64 + c
    int h = t >> 6;
    {
        float w0 = W[2 * t], w1 = W[2 * t + 1];
        float as = att_src[t], ad = att_dst[t];
        sh[0][t] = w0 * as;
        sh[1][t] = w1 * as;
        sh[2][t] = w0 * ad;
        sh[3][t] = w1 * ad;
        sh[4][t] = W_edge[t] * att_edge[t];
    }
    __syncthreads();
    for (int off = 32; off >= 1; off >>= 1) {
        if ((t & 63) < off) {
            #pragma unroll
            for (int k = 0; k < 5; k++) sh[k][t] += sh[k][t + off];
        }
        __syncthreads();
    }
    if ((t & 63) == 0) {
        #pragma unroll
        for (int k = 0; k < 5; k++) cs[k * 4 + h] = sh[k][t];
    }
    __syncthreads();
    if (blockIdx.x == 0) {
        if (t < 20) g_consts[t] = cs[t];
        if (t == 0) g_easum = 0.f;
    }

    int n = blockIdx.x * 256 + t;
    if (n >= N) return;
    float x0 = x[2 * n], x1 = x[2 * n + 1];
    float4 as4, ad4;
    as4.x = x0 * cs[0] + x1 * cs[4];
    as4.y = x0 * cs[1] + x1 * cs[5];
    as4.z = x0 * cs[2] + x1 * cs[6];
    as4.w = x0 * cs[3] + x1 * cs[7];
    ad4.x = x0 * cs[8]  + x1 * cs[12];
    ad4.y = x0 * cs[9]  + x1 * cs[13];
    ad4.z = x0 * cs[10] + x1 * cs[14];
    ad4.w = x0 * cs[11] + x1 * cs[15];
    g_srcpack[2 * n]     = as4;
    g_srcpack[2 * n + 1] = make_float4(x0, x1, 0.f, 0.f);
    g_adst[n] = ad4;
    float4 z = make_float4(0.f, 0.f, 0.f, 0.f);
    g_accum[n * 3 + 0] = z;
    g_accum[n * 3 + 1] = z;
    g_accum[n * 3 + 2] = z;
}

__device__ __forceinline__ void red_v4(float4* p, float a, float b, float c, float d) {
    asm volatile("red.global.add.v4.f32 [%0], {%1,%2,%3,%4};"
                 :: "l"(p), "f"(a), "f"(b), "f"(c), "f"(d) : "memory");
}

// K1: edge pass — softmax weights + factored message accumulation + easum
__global__ void k_edge(const int* __restrict__ ei, const float* __restrict__ ea,
                       int E, int N) {
    float g0 = g_consts[16], g1 = g_consts[17], g2 = g_consts[18], g3 = g_consts[19];
    int stride = gridDim.x * blockDim.x;
    float wsum = 0.f;
    for (int e = blockIdx.x * blockDim.x + threadIdx.x; e < E; e += stride) {
        int src = ei[e];
        int dst = ei[E + e];
        float w = ea[e];
        wsum += w;
        if ((unsigned)src >= (unsigned)N || (unsigned)dst >= (unsigned)N) continue;
        float4 as = g_srcpack[2 * src];
        float4 xs = g_srcpack[2 * src + 1];
        float4 ad = g_adst[dst];

        float a0 = as.x + ad.x + w * g0; a0 = fmaxf(a0, 0.2f * a0);
        float a1 = as.y + ad.y + w * g1; a1 = fmaxf(a1, 0.2f * a1);
        float a2 = as.z + ad.z + w * g2; a2 = fmaxf(a2, 0.2f * a2);
        float a3 = as.w + ad.w + w * g3; a3 = fmaxf(a3, 0.2f * a3);
        float e0 = __expf(a0), e1 = __expf(a1), e2 = __expf(a2), e3 = __expf(a3);

        float4* base = &g_accum[dst * 3];
        red_v4(base,     e0,        e1,        e2,        e3);
        red_v4(base + 1, e0 * xs.x, e1 * xs.x, e2 * xs.x, e3 * xs.x);
        red_v4(base + 2, e0 * xs.y, e1 * xs.y, e2 * xs.y, e3 * xs.y);
    }
    // block-reduce wsum -> g_easum
    #pragma unroll
    for (int o = 16; o; o >>= 1) wsum += __shfl_down_sync(0xffffffffu, wsum, o);
    __shared__ float sh[8];
    if ((threadIdx.x & 31) == 0) sh[threadIdx.x >> 5] = wsum;
    __syncthreads();
    if (threadIdx.x == 0) {
        float s = 0.f;
        #pragma unroll
        for (int i = 0; i < 8; i++) s += sh[i];
        atomicAdd(&g_easum, s);
    }
}

// K2: per-node expansion to [N, 256], self-loop folded in analytically.
// 64 threads per node row, float4 stores; block of 256 covers 4 nodes.
__global__ void k_out(const float* __restrict__ W, const float* __restrict__ bias,
                      float* __restrict__ out, int N, float invE) {
    int t = threadIdx.x;
    int sub = t & 63;           // position within node row (4 floats each)
    int hc0 = sub * 4;          // first of 4 consecutive hc
    int h = hc0 >> 6;           // all 4 hc share one head (64 | 4)
    // per-thread weights: W rows hc0..hc0+3, 2 floats each = 8 consecutive floats
    const float4* W4 = (const float4*)W;
    float4 wa = W4[sub * 2];      // w0[hc0],w1[hc0],w0[hc0+1],w1[hc0+1]
    float4 wb = W4[sub * 2 + 1];  // w0[hc0+2],w1[hc0+2],w0[hc0+3],w1[hc0+3]
    float4 b4 = ((const float4*)bias)[sub];
    float mean = g_easum * invE;
    float gh = g_consts[16 + h];

    int n = blockIdx.x * 4 + (t >> 6);
    if (n >= N) return;

    float4 as4 = g_srcpack[2 * n];
    float4 xs  = g_srcpack[2 * n + 1];
    float4 ad4 = g_adst[n];
    float4 d4  = g_accum[n * 3 + 0];
    float4 t04 = g_accum[n * 3 + 1];
    float4 t14 = g_accum[n * 3 + 2];
    float ash = (h == 0) ? as4.x : (h == 1) ? as4.y : (h == 2) ? as4.z : as4.w;
    float adh = (h == 0) ? ad4.x : (h == 1) ? ad4.y : (h == 2) ? ad4.z : ad4.w;
    float dh  = (h == 0) ? d4.x  : (h == 1) ? d4.y  : (h == 2) ? d4.z  : d4.w;
    float t0h = (h == 0) ? t04.x : (h == 1) ? t04.y : (h == 2) ? t04.z : t04.w;
    float t1h = (h == 0) ? t14.x : (h == 1) ? t14.y : (h == 2) ? t14.z : t14.w;

    float a = ash + adh + mean * gh;   // self-loop logit
    a = fmaxf(a, 0.2f * a);
    float ws = __expf(a);
    float rdenom = 1.0f / (dh + ws);
    float T0 = (t0h + ws * xs.x) * rdenom;
    float T1 = (t1h + ws * xs.y) * rdenom;

    float4 o;
    o.x = T0 * wa.x + T1 * wa.y + b4.x;
    o.y = T0 * wa.z + T1 * wa.w + b4.y;
    o.z = T0 * wb.x + T1 * wb.y + b4.z;
    o.w = T0 * wb.z + T1 * wb.w + b4.w;
    ((float4*)out)[(size_t)n * 64 + sub] = o;
}

extern "C" void kernel_launch(void* const* d_in, const int* in_sizes, int n_in,
                              void* d_out, int out_size) {
    const float* x        = (const float*)d_in[0];
    const int*   ei       = (const int*)d_in[1];     // int32 (JAX x64 off)
    const float* ea       = (const float*)d_in[2];
    const float* W        = (const float*)d_in[3];
    const float* att_src  = (const float*)d_in[4];
    const float* att_dst  = (const float*)d_in[5];
    const float* W_edge   = (const float*)d_in[6];
    const float* att_edge = (const float*)d_in[7];
    const float* bias     = (const float*)d_in[8];
    int N = in_sizes[0] / 2;
    int E = in_sizes[2];
    float* out = (float*)d_out;

    k_prep<<<(N + 255) / 256, 256>>>(x, W, att_src, att_dst, W_edge, att_edge, N);
    k_edge<<<(E + 255) / 256, 256>>>(ei, ea, E, N);
    k_out<<<(N + 3) / 4, 256>>>(W, bias, out, N, 1.0f / (float)E);
}